// round 15
// baseline (speedup 1.0000x reference)
#include <cuda_runtime.h>
#include <cuda_fp16.h>
#include <math.h>

// ---------------------------------------------------------------------------
// LightGCN pipeline v3:
//   Wp   = pack(W even-k, odd-k); zero counters  (k_prep, fused)
//   xw   = feats @ W  via fma.rn.f32x2 -> fp16   (k_gemm)
//   CSR build: histogram(int4) -> scan -> scatter(int4)
//   h row = sum val*xw_h[col]; fused tanh+l2norm (k_csr, warp/row, x4 unroll)
//   bpr   = sum softplus(-(y_ui-y_uj))           (k_bpr)
//   loss  = (bpr + 0.5*wd*sumsq)/B               (k_final)
// xw stored as fp16 (half2 per dim-pair): halves the 819MB L2 gather in k_csr.
// ---------------------------------------------------------------------------

#define NMAX 100000
#define EMAX 3200000
#define SCAN_BLK 2048

typedef unsigned long long ull;

__device__ __half2 g_xwh[NMAX * 32];   // xw in fp16  (12.8 MB)
__device__ float4  g_emb4[NMAX * 16];  // emb fp32    (25.6 MB)
__device__ int2    g_scv[EMAX];        // sorted (col, val_f32) pairs (25.6 MB)
__device__ ull     g_Wp[128 * 64];     // packed W: (W[2k][d], W[2k+1][d])
__device__ int     g_cnt[NMAX];
__device__ int     g_rowptr[NMAX + 1];
__device__ int     g_wcur[NMAX];
__device__ int     g_pre[NMAX];
__device__ int     g_bsum[64];
__device__ int     g_boff[64];
__device__ float   g_bpr;
__device__ float   g_sumsq;

// ---- f32x2 helpers --------------------------------------------------------
__device__ __forceinline__ ull pk(float lo, float hi) {
    ull r; asm("mov.b64 %0, {%1,%2};" : "=l"(r) : "f"(lo), "f"(hi)); return r;
}
__device__ __forceinline__ float2 unpk(ull v) {
    float2 f; asm("mov.b64 {%0,%1}, %2;" : "=f"(f.x), "=f"(f.y) : "l"(v)); return f;
}
__device__ __forceinline__ ull f2fma(ull a, ull b, ull c) {
    ull d; asm("fma.rn.f32x2 %0, %1, %2, %3;" : "=l"(d) : "l"(a), "l"(b), "l"(c)); return d;
}

// ---- prep: zero counters/scalars + pack W ----------------------------------
__global__ void __launch_bounds__(256) k_prep(const float* __restrict__ W, int N) {
    int i = blockIdx.x * 256 + threadIdx.x;
    if (i < N) g_cnt[i] = 0;
    if (i < 128 * 64) {
        int k2 = i >> 6, d = i & 63;
        g_Wp[i] = pk(W[(2 * k2) * 64 + d], W[(2 * k2 + 1) * 64 + d]);
    }
    if (i == 0) { g_bpr = 0.f; g_sumsq = 0.f; }
}

// ---- GEMM: xw[N,64] = feats[N,256] @ W via FFMA2, output fp16 --------------
__global__ void __launch_bounds__(256) k_gemm(const float* __restrict__ feats,
                                              int N) {
    __shared__ float sx[32 * 256];
    const int tile = blockIdx.x * 32;

    float4* d4 = (float4*)sx;
    const float4* src = (const float4*)feats + (size_t)tile * 64;
    if (tile + 32 <= N) {
#pragma unroll
        for (int j = 0; j < 8; ++j)
            d4[threadIdx.x + j * 256] = src[threadIdx.x + j * 256];
    } else {
#pragma unroll
        for (int j = 0; j < 8; ++j) {
            int f = threadIdx.x + j * 256;
            int row = tile + (f >> 6);
            float4 v = make_float4(0.f, 0.f, 0.f, 0.f);
            if (row < N) v = src[f];
            d4[f] = v;
        }
    }
    __syncthreads();

    const int warp = threadIdx.x >> 5, lane = threadIdx.x & 31;
    const int r0 = warp * 4, d0 = lane * 2;
    const float* sx0 = sx + r0 * 256;

    ull a00 = 0, a01 = 0, a10 = 0, a11 = 0, a20 = 0, a21 = 0, a30 = 0, a31 = 0;

    for (int k = 0; k < 256; k += 4) {
        float4 x0 = *(const float4*)(sx0 + k);
        float4 x1 = *(const float4*)(sx0 + 256 + k);
        float4 x2 = *(const float4*)(sx0 + 512 + k);
        float4 x3 = *(const float4*)(sx0 + 768 + k);
        const ull* wp = g_Wp + (k >> 1) * 64 + d0;
        ulonglong2 w0 = *(const ulonglong2*)(wp);
        ulonglong2 w1 = *(const ulonglong2*)(wp + 64);

        ull p;
        p = pk(x0.x, x0.y); a00 = f2fma(p, w0.x, a00); a01 = f2fma(p, w0.y, a01);
        p = pk(x0.z, x0.w); a00 = f2fma(p, w1.x, a00); a01 = f2fma(p, w1.y, a01);
        p = pk(x1.x, x1.y); a10 = f2fma(p, w0.x, a10); a11 = f2fma(p, w0.y, a11);
        p = pk(x1.z, x1.w); a10 = f2fma(p, w1.x, a10); a11 = f2fma(p, w1.y, a11);
        p = pk(x2.x, x2.y); a20 = f2fma(p, w0.x, a20); a21 = f2fma(p, w0.y, a21);
        p = pk(x2.z, x2.w); a20 = f2fma(p, w1.x, a20); a21 = f2fma(p, w1.y, a21);
        p = pk(x3.x, x3.y); a30 = f2fma(p, w0.x, a30); a31 = f2fma(p, w0.y, a31);
        p = pk(x3.z, x3.w); a30 = f2fma(p, w1.x, a30); a31 = f2fma(p, w1.y, a31);
    }

    ull acc[4][2] = {{a00, a01}, {a10, a11}, {a20, a21}, {a30, a31}};
#pragma unroll
    for (int r = 0; r < 4; ++r) {
        int row = tile + r0 + r;
        if (row < N) {
            float2 e0 = unpk(acc[r][0]), e1 = unpk(acc[r][1]);
            g_xwh[(size_t)row * 32 + lane] =
                __floats2half2_rn(e0.x + e0.y, e1.x + e1.y);
        }
    }
}

// ---- histogram of edge rows (4 edges / thread) ------------------------------
__global__ void __launch_bounds__(256) k_hist4(const int4* __restrict__ erow4, int E4) {
    int i = blockIdx.x * 256 + threadIdx.x;
    if (i < E4) {
        int4 r = __ldg(erow4 + i);
        atomicAdd(&g_cnt[r.x], 1);
        atomicAdd(&g_cnt[r.y], 1);
        atomicAdd(&g_cnt[r.z], 1);
        atomicAdd(&g_cnt[r.w], 1);
    }
}
__global__ void k_hist_tail(const int* __restrict__ erow, int start, int E) {
    int e = start + threadIdx.x;
    if (e < E) atomicAdd(&g_cnt[erow[e]], 1);
}

// ---- scan phase A: per-block (2048-elem) exclusive prescan + block sums -----
__global__ void __launch_bounds__(256) k_scanA(int N) {
    __shared__ int wsum[8];
    __shared__ int wexc[8];
    int base = blockIdx.x * SCAN_BLK + threadIdx.x * 8;
    int vals[8];
    int local = 0;
#pragma unroll
    for (int j = 0; j < 8; ++j) {
        int idx = base + j;
        int c = (idx < N) ? g_cnt[idx] : 0;
        vals[j] = local;
        local += c;
    }
    int lane = threadIdx.x & 31, w = threadIdx.x >> 5;
    int inc = local;
#pragma unroll
    for (int o = 1; o < 32; o <<= 1) {
        int y = __shfl_up_sync(0xffffffffu, inc, o);
        if (lane >= o) inc += y;
    }
    if (lane == 31) wsum[w] = inc;
    __syncthreads();
    if (w == 0 && lane < 8) {
        int v = wsum[lane];
        int s = v;
#pragma unroll
        for (int o = 1; o < 8; o <<= 1) {
            int y = __shfl_up_sync(0x000000ffu, s, o);
            if (lane >= o) s += y;
        }
        wexc[lane] = s - v;
        if (lane == 7) g_bsum[blockIdx.x] = s;
    }
    __syncthreads();
    int toff = wexc[w] + (inc - local);
#pragma unroll
    for (int j = 0; j < 8; ++j) {
        int idx = base + j;
        if (idx < N) g_pre[idx] = toff + vals[j];
    }
}

// ---- scan phase B: exclusive scan of <=64 block sums (1 warp) ---------------
__global__ void k_scanB(int nb) {
    int lane = threadIdx.x;
    int v0 = (lane < nb) ? g_bsum[lane] : 0;
    int v1 = (lane + 32 < nb) ? g_bsum[lane + 32] : 0;
    int s0 = v0, s1 = v1;
#pragma unroll
    for (int o = 1; o < 32; o <<= 1) {
        int y0 = __shfl_up_sync(0xffffffffu, s0, o);
        int y1 = __shfl_up_sync(0xffffffffu, s1, o);
        if (lane >= o) { s0 += y0; s1 += y1; }
    }
    int tot0 = __shfl_sync(0xffffffffu, s0, 31);
    if (lane < nb) g_boff[lane] = s0 - v0;
    if (lane + 32 < nb) g_boff[lane + 32] = tot0 + s1 - v1;
}

// ---- scan phase C: finalize rowptr + write cursor ---------------------------
__global__ void __launch_bounds__(256) k_scanC(int N, int E) {
    int i = blockIdx.x * 256 + threadIdx.x;
    if (i < N) {
        int v = g_pre[i] + g_boff[i >> 11];
        g_rowptr[i] = v;
        g_wcur[i] = v;
    }
    if (i == N) g_rowptr[N] = E;
}

// ---- scatter edges into CSR order (4 edges / thread) ------------------------
__global__ void __launch_bounds__(256) k_scatter4(const int4* __restrict__ erow4,
                                                  const int4* __restrict__ ecol4,
                                                  const float4* __restrict__ ev4,
                                                  int E4) {
    int i = blockIdx.x * 256 + threadIdx.x;
    if (i >= E4) return;
    int4 r = __ldg(erow4 + i);
    int4 c = __ldg(ecol4 + i);
    float4 v = __ldg(ev4 + i);
    int p;
    p = atomicAdd(&g_wcur[r.x], 1); g_scv[p] = make_int2(c.x, __float_as_int(v.x));
    p = atomicAdd(&g_wcur[r.y], 1); g_scv[p] = make_int2(c.y, __float_as_int(v.y));
    p = atomicAdd(&g_wcur[r.z], 1); g_scv[p] = make_int2(c.z, __float_as_int(v.z));
    p = atomicAdd(&g_wcur[r.w], 1); g_scv[p] = make_int2(c.w, __float_as_int(v.w));
}
__global__ void k_scatter_tail(const int* __restrict__ erow,
                               const int* __restrict__ ecol,
                               const float* __restrict__ ev,
                               int start, int E) {
    int e = start + threadIdx.x;
    if (e >= E) return;
    int p = atomicAdd(&g_wcur[erow[e]], 1);
    g_scv[p] = make_int2(ecol[e], __float_as_int(ev[e]));
}

// ---- CSR SpMM (fp16 gather) + fused tanh + l2-normalize + sum(emb^2) --------
// Warp per row, lane -> 2 dims. Edge loop unrolled x4 for MLP=4 on the gathers.
__global__ void __launch_bounds__(256) k_csr(int N) {
    __shared__ float part[8];
    const int w = threadIdx.x >> 5, lane = threadIdx.x & 31;
    const int r = blockIdx.x * 8 + w;
    float rowsq = 0.f;
    if (r < N) {
        const int s0 = g_rowptr[r], s1 = g_rowptr[r + 1];
        const __half2* __restrict__ xwh = g_xwh;
        float a0x = 0.f, a0y = 0.f, a1x = 0.f, a1y = 0.f;
        float a2x = 0.f, a2y = 0.f, a3x = 0.f, a3y = 0.f;
        for (int base = s0; base < s1; base += 32) {
            int n = s1 - base; if (n > 32) n = 32;
            int2 cv = make_int2(0, 0);
            if (lane < n) cv = __ldg(&g_scv[base + lane]);
            int j = 0;
            for (; j + 3 < n; j += 4) {
                int   c0 = __shfl_sync(0xffffffffu, cv.x, j);
                float v0 = __int_as_float(__shfl_sync(0xffffffffu, cv.y, j));
                int   c1 = __shfl_sync(0xffffffffu, cv.x, j + 1);
                float v1 = __int_as_float(__shfl_sync(0xffffffffu, cv.y, j + 1));
                int   c2 = __shfl_sync(0xffffffffu, cv.x, j + 2);
                float v2 = __int_as_float(__shfl_sync(0xffffffffu, cv.y, j + 2));
                int   c3 = __shfl_sync(0xffffffffu, cv.x, j + 3);
                float v3 = __int_as_float(__shfl_sync(0xffffffffu, cv.y, j + 3));
                __half2 h0 = __ldg(xwh + (size_t)c0 * 32 + lane);
                __half2 h1 = __ldg(xwh + (size_t)c1 * 32 + lane);
                __half2 h2 = __ldg(xwh + (size_t)c2 * 32 + lane);
                __half2 h3 = __ldg(xwh + (size_t)c3 * 32 + lane);
                float2 x0 = __half22float2(h0);
                float2 x1 = __half22float2(h1);
                float2 x2 = __half22float2(h2);
                float2 x3 = __half22float2(h3);
                a0x = fmaf(v0, x0.x, a0x); a0y = fmaf(v0, x0.y, a0y);
                a1x = fmaf(v1, x1.x, a1x); a1y = fmaf(v1, x1.y, a1y);
                a2x = fmaf(v2, x2.x, a2x); a2y = fmaf(v2, x2.y, a2y);
                a3x = fmaf(v3, x3.x, a3x); a3y = fmaf(v3, x3.y, a3y);
            }
            for (; j < n; ++j) {
                int   c0 = __shfl_sync(0xffffffffu, cv.x, j);
                float v0 = __int_as_float(__shfl_sync(0xffffffffu, cv.y, j));
                float2 x0 = __half22float2(__ldg(xwh + (size_t)c0 * 32 + lane));
                a0x = fmaf(v0, x0.x, a0x); a0y = fmaf(v0, x0.y, a0y);
            }
        }
        float tx = tanhf((a0x + a1x) + (a2x + a3x));
        float ty = tanhf((a0y + a1y) + (a2y + a3y));
        float sq = fmaf(tx, tx, ty * ty);
#pragma unroll
        for (int o = 16; o; o >>= 1) sq += __shfl_xor_sync(0xffffffffu, sq, o);
        float sc = rsqrtf(fmaxf(sq, 1e-12f));
        float* emb = (float*)g_emb4;
        *(float2*)(emb + (size_t)r * 64 + lane * 2) = make_float2(tx * sc, ty * sc);
        rowsq = sq * sc * sc;
    }
    if (lane == 0) part[w] = (r < N) ? rowsq : 0.f;
    __syncthreads();
    if (threadIdx.x == 0) {
        float s = 0.f;
#pragma unroll
        for (int i = 0; i < 8; ++i) s += part[i];
        atomicAdd(&g_sumsq, s);
    }
}

// ---- BPR --------------------------------------------------------------------
__global__ void __launch_bounds__(256) k_bpr(const int* __restrict__ i1v,
                                             const int* __restrict__ i2v,
                                             const int* __restrict__ inv,
                                             int B) {
    __shared__ float part[8];
    const int gw = (blockIdx.x * 256 + threadIdx.x) >> 5;
    const int lane = threadIdx.x & 31;
    float term = 0.f;
    if (gw < B) {
        const float* emb = (const float*)g_emb4;
        int i1 = __ldg(i1v + gw), i2 = __ldg(i2v + gw), ineg = __ldg(inv + gw);
        float2 o1 = *(const float2*)(emb + (size_t)i1 * 64 + lane * 2);
        float2 o2 = *(const float2*)(emb + (size_t)i2 * 64 + lane * 2);
        float2 on = *(const float2*)(emb + (size_t)ineg * 64 + lane * 2);
        float ui = fmaf(o1.x, o2.x, o1.y * o2.y);
        float uj = fmaf(o1.x, on.x, o1.y * on.y);
#pragma unroll
        for (int o = 16; o; o >>= 1) {
            ui += __shfl_xor_sync(0xffffffffu, ui, o);
            uj += __shfl_xor_sync(0xffffffffu, uj, o);
        }
        float z = uj - ui;
        term = fmaxf(z, 0.f) + log1pf(expf(-fabsf(z)));
    }
    if (lane == 0) part[threadIdx.x >> 5] = term;
    __syncthreads();
    if (threadIdx.x == 0) {
        float s = 0.f;
#pragma unroll
        for (int i = 0; i < 8; ++i) s += part[i];
        atomicAdd(&g_bpr, s);
    }
}

// ---- finalize -----------------------------------------------------------------
__global__ void k_final(float* __restrict__ out, float invB) {
    out[0] = (g_bpr + 5e-5f * g_sumsq) * invB;   // wd*0.5 = 5e-5
}

// ---------------------------------------------------------------------------
extern "C" void kernel_launch(void* const* d_in, const int* in_sizes, int n_in,
                              void* d_out, int out_size) {
    const float* feats = (const float*)d_in[0];
    const float* W     = (const float*)d_in[1];
    const int*   erow  = (const int*)d_in[2];
    const int*   ecol  = (const int*)d_in[3];
    const float* evalv = (const float*)d_in[4];
    const int*   idx1  = (const int*)d_in[5];
    const int*   idx2  = (const int*)d_in[6];
    const int*   negi  = (const int*)d_in[7];

    const int N = in_sizes[0] / 256;   // 100000
    const int E = in_sizes[2];         // 3200000
    const int B = in_sizes[5];         // 4096
    const int E4 = E >> 2, Erem = E & 3;
    const int nbA = (N + SCAN_BLK - 1) / SCAN_BLK;   // 49

    k_prep<<<(N + 255) / 256, 256>>>(W, N);
    k_gemm<<<(N + 31) / 32, 256>>>(feats, N);
    k_hist4<<<(E4 + 255) / 256, 256>>>((const int4*)erow, E4);
    if (Erem) k_hist_tail<<<1, 32>>>(erow, E4 * 4, E);
    k_scanA<<<nbA, 256>>>(N);
    k_scanB<<<1, 32>>>(nbA);
    k_scanC<<<(N + 1 + 255) / 256, 256>>>(N, E);
    k_scatter4<<<(E4 + 255) / 256, 256>>>((const int4*)erow, (const int4*)ecol,
                                          (const float4*)evalv, E4);
    if (Erem) k_scatter_tail<<<1, 32>>>(erow, ecol, evalv, E4 * 4, E);
    k_csr<<<(N + 7) / 8, 256>>>(N);
    k_bpr<<<(B + 7) / 8, 256>>>(idx1, idx2, negi, B);
    k_final<<<1, 1>>>((float*)d_out, 1.0f / (float)B);
}

// round 16
// speedup vs baseline: 1.0721x; 1.0721x over previous
#include <cuda_runtime.h>
#include <cuda_fp16.h>
#include <math.h>

// ---------------------------------------------------------------------------
// LightGCN pipeline v4:
//   k_prep   : zero counters/scalars + pack W into f32x2 pairs
//   k_hist   : row histogram (1 edge/thread, spread atomics)
//   k_scanA/B/C : exclusive scan -> rowptr + write cursors
//   k_gemm   : xw = feats @ W via fma.rn.f32x2, fp16 output   [launch #4 -> ncu]
//   k_scatter: counting-sort edges into CSR order (1 edge/thread)
//   k_csr    : warp/row register SpMM (unroll-8 gather groups) + tanh + l2norm
//   k_bpr    : BPR softplus reduction
//   k_final  : loss = (bpr + 0.5*wd*sumsq)/B
// ---------------------------------------------------------------------------

#define NMAX 100000
#define EMAX 3200000
#define SCAN_BLK 2048

typedef unsigned long long ull;

__device__ __half2 g_xwh[NMAX * 32];   // xw in fp16  (12.8 MB)
__device__ float4  g_emb4[NMAX * 16];  // emb fp32    (25.6 MB)
__device__ int2    g_scv[EMAX];        // CSR-ordered (col, val_f32) (25.6 MB)
__device__ ull     g_Wp[128 * 64];     // packed W: (W[2k][d], W[2k+1][d])
__device__ int     g_cnt[NMAX];
__device__ int     g_rowptr[NMAX + 1];
__device__ int     g_wcur[NMAX];
__device__ int     g_pre[NMAX];
__device__ int     g_bsum[64];
__device__ int     g_boff[64];
__device__ float   g_bpr;
__device__ float   g_sumsq;

// ---- f32x2 helpers --------------------------------------------------------
__device__ __forceinline__ ull pk(float lo, float hi) {
    ull r; asm("mov.b64 %0, {%1,%2};" : "=l"(r) : "f"(lo), "f"(hi)); return r;
}
__device__ __forceinline__ float2 unpk(ull v) {
    float2 f; asm("mov.b64 {%0,%1}, %2;" : "=f"(f.x), "=f"(f.y) : "l"(v)); return f;
}
__device__ __forceinline__ ull f2fma(ull a, ull b, ull c) {
    ull d; asm("fma.rn.f32x2 %0, %1, %2, %3;" : "=l"(d) : "l"(a), "l"(b), "l"(c)); return d;
}

// ---- prep: zero counters/scalars + pack W ---------------------------------
__global__ void __launch_bounds__(256) k_prep(const float* __restrict__ W, int N) {
    int i = blockIdx.x * 256 + threadIdx.x;
    if (i < N) g_cnt[i] = 0;
    if (i < 128 * 64) {
        int k2 = i >> 6, d = i & 63;
        g_Wp[i] = pk(W[(2 * k2) * 64 + d], W[(2 * k2 + 1) * 64 + d]);
    }
    if (i == 0) { g_bpr = 0.f; g_sumsq = 0.f; }
}

// ---- histogram of edge rows (1 edge / thread) ------------------------------
__global__ void __launch_bounds__(256) k_hist(const int* __restrict__ erow, int E) {
    int e = blockIdx.x * 256 + threadIdx.x;
    if (e < E) atomicAdd(&g_cnt[erow[e]], 1);
}

// ---- scan phase A ----------------------------------------------------------
__global__ void __launch_bounds__(256) k_scanA(int N) {
    __shared__ int wsum[8];
    __shared__ int wexc[8];
    int base = blockIdx.x * SCAN_BLK + threadIdx.x * 8;
    int vals[8];
    int local = 0;
#pragma unroll
    for (int j = 0; j < 8; ++j) {
        int idx = base + j;
        int c = (idx < N) ? g_cnt[idx] : 0;
        vals[j] = local;
        local += c;
    }
    int lane = threadIdx.x & 31, w = threadIdx.x >> 5;
    int inc = local;
#pragma unroll
    for (int o = 1; o < 32; o <<= 1) {
        int y = __shfl_up_sync(0xffffffffu, inc, o);
        if (lane >= o) inc += y;
    }
    if (lane == 31) wsum[w] = inc;
    __syncthreads();
    if (w == 0 && lane < 8) {
        int v = wsum[lane];
        int s = v;
#pragma unroll
        for (int o = 1; o < 8; o <<= 1) {
            int y = __shfl_up_sync(0x000000ffu, s, o);
            if (lane >= o) s += y;
        }
        wexc[lane] = s - v;
        if (lane == 7) g_bsum[blockIdx.x] = s;
    }
    __syncthreads();
    int toff = wexc[w] + (inc - local);
#pragma unroll
    for (int j = 0; j < 8; ++j) {
        int idx = base + j;
        if (idx < N) g_pre[idx] = toff + vals[j];
    }
}

// ---- GEMM: xw[N,64] = feats[N,256] @ W via FFMA2, fp16 out -----------------
__global__ void __launch_bounds__(256) k_gemm(const float* __restrict__ feats,
                                              int N) {
    __shared__ float sx[32 * 256];
    const int tile = blockIdx.x * 32;

    float4* d4 = (float4*)sx;
    const float4* src = (const float4*)feats + (size_t)tile * 64;
    if (tile + 32 <= N) {
#pragma unroll
        for (int j = 0; j < 8; ++j)
            d4[threadIdx.x + j * 256] = src[threadIdx.x + j * 256];
    } else {
#pragma unroll
        for (int j = 0; j < 8; ++j) {
            int f = threadIdx.x + j * 256;
            int row = tile + (f >> 6);
            float4 v = make_float4(0.f, 0.f, 0.f, 0.f);
            if (row < N) v = src[f];
            d4[f] = v;
        }
    }
    __syncthreads();

    const int warp = threadIdx.x >> 5, lane = threadIdx.x & 31;
    const int r0 = warp * 4, d0 = lane * 2;
    const float* sx0 = sx + r0 * 256;

    ull a00 = 0, a01 = 0, a10 = 0, a11 = 0, a20 = 0, a21 = 0, a30 = 0, a31 = 0;

    for (int k = 0; k < 256; k += 4) {
        float4 x0 = *(const float4*)(sx0 + k);
        float4 x1 = *(const float4*)(sx0 + 256 + k);
        float4 x2 = *(const float4*)(sx0 + 512 + k);
        float4 x3 = *(const float4*)(sx0 + 768 + k);
        const ull* wp = g_Wp + (k >> 1) * 64 + d0;
        ulonglong2 w0 = *(const ulonglong2*)(wp);
        ulonglong2 w1 = *(const ulonglong2*)(wp + 64);

        ull p;
        p = pk(x0.x, x0.y); a00 = f2fma(p, w0.x, a00); a01 = f2fma(p, w0.y, a01);
        p = pk(x0.z, x0.w); a00 = f2fma(p, w1.x, a00); a01 = f2fma(p, w1.y, a01);
        p = pk(x1.x, x1.y); a10 = f2fma(p, w0.x, a10); a11 = f2fma(p, w0.y, a11);
        p = pk(x1.z, x1.w); a10 = f2fma(p, w1.x, a10); a11 = f2fma(p, w1.y, a11);
        p = pk(x2.x, x2.y); a20 = f2fma(p, w0.x, a20); a21 = f2fma(p, w0.y, a21);
        p = pk(x2.z, x2.w); a20 = f2fma(p, w1.x, a20); a21 = f2fma(p, w1.y, a21);
        p = pk(x3.x, x3.y); a30 = f2fma(p, w0.x, a30); a31 = f2fma(p, w0.y, a31);
        p = pk(x3.z, x3.w); a30 = f2fma(p, w1.x, a30); a31 = f2fma(p, w1.y, a31);
    }

    ull acc[4][2] = {{a00, a01}, {a10, a11}, {a20, a21}, {a30, a31}};
#pragma unroll
    for (int r = 0; r < 4; ++r) {
        int row = tile + r0 + r;
        if (row < N) {
            float2 e0 = unpk(acc[r][0]), e1 = unpk(acc[r][1]);
            g_xwh[(size_t)row * 32 + lane] =
                __floats2half2_rn(e0.x + e0.y, e1.x + e1.y);
        }
    }
}

// ---- scan phase B ----------------------------------------------------------
__global__ void k_scanB(int nb) {
    int lane = threadIdx.x;
    int v0 = (lane < nb) ? g_bsum[lane] : 0;
    int v1 = (lane + 32 < nb) ? g_bsum[lane + 32] : 0;
    int s0 = v0, s1 = v1;
#pragma unroll
    for (int o = 1; o < 32; o <<= 1) {
        int y0 = __shfl_up_sync(0xffffffffu, s0, o);
        int y1 = __shfl_up_sync(0xffffffffu, s1, o);
        if (lane >= o) { s0 += y0; s1 += y1; }
    }
    int tot0 = __shfl_sync(0xffffffffu, s0, 31);
    if (lane < nb) g_boff[lane] = s0 - v0;
    if (lane + 32 < nb) g_boff[lane + 32] = tot0 + s1 - v1;
}

// ---- scan phase C ----------------------------------------------------------
__global__ void __launch_bounds__(256) k_scanC(int N, int E) {
    int i = blockIdx.x * 256 + threadIdx.x;
    if (i < N) {
        int v = g_pre[i] + g_boff[i >> 11];
        g_rowptr[i] = v;
        g_wcur[i] = v;
    }
    if (i == N) g_rowptr[N] = E;
}

// ---- scatter edges into CSR order (1 edge / thread) ------------------------
__global__ void __launch_bounds__(256) k_scatter(const int* __restrict__ erow,
                                                 const int* __restrict__ ecol,
                                                 const float* __restrict__ ev,
                                                 int E) {
    int e = blockIdx.x * 256 + threadIdx.x;
    if (e >= E) return;
    int r = erow[e];
    int pos = atomicAdd(&g_wcur[r], 1);
    g_scv[pos] = make_int2(ecol[e], __float_as_int(ev[e]));
}

// ---- CSR SpMM (fp16 gather, unroll-8 groups) + tanh + l2norm + sumsq ------
// Warp per row, lane -> 2 dims. Full 32-edge batches run a fixed-trip loop of
// 4 groups x 8 independent gathers (MLP=8). Remainder uses 4-groups + scalar.
__global__ void __launch_bounds__(256) k_csr(int N) {
    __shared__ float part[8];
    const int w = threadIdx.x >> 5, lane = threadIdx.x & 31;
    const int r = blockIdx.x * 8 + w;
    float rowsq = 0.f;
    if (r < N) {
        const int s0 = g_rowptr[r], s1 = g_rowptr[r + 1];
        const __half2* __restrict__ xwh = g_xwh;
        float ax[4] = {0.f, 0.f, 0.f, 0.f};
        float ay[4] = {0.f, 0.f, 0.f, 0.f};

        int base = s0;
        // ---- full 32-edge batches (fixed trip count) ----
        for (; base + 32 <= s1; base += 32) {
            int2 cv = __ldg(&g_scv[base + lane]);
#pragma unroll
            for (int j = 0; j < 32; j += 8) {
                int   c[8]; float v[8];
#pragma unroll
                for (int t = 0; t < 8; ++t) {
                    c[t] = __shfl_sync(0xffffffffu, cv.x, j + t);
                    v[t] = __int_as_float(__shfl_sync(0xffffffffu, cv.y, j + t));
                }
                __half2 h[8];
#pragma unroll
                for (int t = 0; t < 8; ++t)
                    h[t] = __ldg(xwh + (size_t)c[t] * 32 + lane);
#pragma unroll
                for (int t = 0; t < 8; ++t) {
                    float2 x = __half22float2(h[t]);
                    ax[t & 3] = fmaf(v[t], x.x, ax[t & 3]);
                    ay[t & 3] = fmaf(v[t], x.y, ay[t & 3]);
                }
            }
        }
        // ---- remainder (< 32 edges) ----
        int n = s1 - base;
        if (n > 0) {
            int2 cv = make_int2(0, 0);
            if (lane < n) cv = __ldg(&g_scv[base + lane]);
            int j = 0;
            for (; j + 3 < n; j += 4) {
                int   c[4]; float v[4];
#pragma unroll
                for (int t = 0; t < 4; ++t) {
                    c[t] = __shfl_sync(0xffffffffu, cv.x, j + t);
                    v[t] = __int_as_float(__shfl_sync(0xffffffffu, cv.y, j + t));
                }
                __half2 h[4];
#pragma unroll
                for (int t = 0; t < 4; ++t)
                    h[t] = __ldg(xwh + (size_t)c[t] * 32 + lane);
#pragma unroll
                for (int t = 0; t < 4; ++t) {
                    float2 x = __half22float2(h[t]);
                    ax[t] = fmaf(v[t], x.x, ax[t]);
                    ay[t] = fmaf(v[t], x.y, ay[t]);
                }
            }
            for (; j < n; ++j) {
                int   c0 = __shfl_sync(0xffffffffu, cv.x, j);
                float v0 = __int_as_float(__shfl_sync(0xffffffffu, cv.y, j));
                float2 x = __half22float2(__ldg(xwh + (size_t)c0 * 32 + lane));
                ax[0] = fmaf(v0, x.x, ax[0]);
                ay[0] = fmaf(v0, x.y, ay[0]);
            }
        }

        float tx = tanhf((ax[0] + ax[1]) + (ax[2] + ax[3]));
        float ty = tanhf((ay[0] + ay[1]) + (ay[2] + ay[3]));
        float sq = fmaf(tx, tx, ty * ty);
#pragma unroll
        for (int o = 16; o; o >>= 1) sq += __shfl_xor_sync(0xffffffffu, sq, o);
        float sc = rsqrtf(fmaxf(sq, 1e-12f));
        float* emb = (float*)g_emb4;
        *(float2*)(emb + (size_t)r * 64 + lane * 2) = make_float2(tx * sc, ty * sc);
        rowsq = sq * sc * sc;
    }
    if (lane == 0) part[w] = (r < N) ? rowsq : 0.f;
    __syncthreads();
    if (threadIdx.x == 0) {
        float s = 0.f;
#pragma unroll
        for (int i = 0; i < 8; ++i) s += part[i];
        atomicAdd(&g_sumsq, s);
    }
}

// ---- BPR -------------------------------------------------------------------
__global__ void __launch_bounds__(256) k_bpr(const int* __restrict__ i1v,
                                             const int* __restrict__ i2v,
                                             const int* __restrict__ inv,
                                             int B) {
    __shared__ float part[8];
    const int gw = (blockIdx.x * 256 + threadIdx.x) >> 5;
    const int lane = threadIdx.x & 31;
    float term = 0.f;
    if (gw < B) {
        const float* emb = (const float*)g_emb4;
        int i1 = __ldg(i1v + gw), i2 = __ldg(i2v + gw), ineg = __ldg(inv + gw);
        float2 o1 = *(const float2*)(emb + (size_t)i1 * 64 + lane * 2);
        float2 o2 = *(const float2*)(emb + (size_t)i2 * 64 + lane * 2);
        float2 on = *(const float2*)(emb + (size_t)ineg * 64 + lane * 2);
        float ui = fmaf(o1.x, o2.x, o1.y * o2.y);
        float uj = fmaf(o1.x, on.x, o1.y * on.y);
#pragma unroll
        for (int o = 16; o; o >>= 1) {
            ui += __shfl_xor_sync(0xffffffffu, ui, o);
            uj += __shfl_xor_sync(0xffffffffu, uj, o);
        }
        float z = uj - ui;
        term = fmaxf(z, 0.f) + log1pf(expf(-fabsf(z)));
    }
    if (lane == 0) part[threadIdx.x >> 5] = term;
    __syncthreads();
    if (threadIdx.x == 0) {
        float s = 0.f;
#pragma unroll
        for (int i = 0; i < 8; ++i) s += part[i];
        atomicAdd(&g_bpr, s);
    }
}

// ---- finalize ---------------------------------------------------------------
__global__ void k_final(float* __restrict__ out, float invB) {
    out[0] = (g_bpr + 5e-5f * g_sumsq) * invB;   // wd*0.5 = 5e-5
}

// ---------------------------------------------------------------------------
extern "C" void kernel_launch(void* const* d_in, const int* in_sizes, int n_in,
                              void* d_out, int out_size) {
    const float* feats = (const float*)d_in[0];
    const float* W     = (const float*)d_in[1];
    const int*   erow  = (const int*)d_in[2];
    const int*   ecol  = (const int*)d_in[3];
    const float* evalv = (const float*)d_in[4];
    const int*   idx1  = (const int*)d_in[5];
    const int*   idx2  = (const int*)d_in[6];
    const int*   negi  = (const int*)d_in[7];

    const int N = in_sizes[0] / 256;   // 100000
    const int E = in_sizes[2];         // 3200000
    const int B = in_sizes[5];         // 4096
    const int nbA = (N + SCAN_BLK - 1) / SCAN_BLK;   // 49

    k_prep<<<(N + 255) / 256, 256>>>(W, N);                 // #1
    k_hist<<<(E + 255) / 256, 256>>>(erow, E);              // #2
    k_scanA<<<nbA, 256>>>(N);                               // #3
    k_gemm<<<(N + 31) / 32, 256>>>(feats, N);               // #4  <- profiled
    k_scanB<<<1, 32>>>(nbA);                                // #5
    k_scanC<<<(N + 1 + 255) / 256, 256>>>(N, E);            // #6
    k_scatter<<<(E + 255) / 256, 256>>>(erow, ecol, evalv, E); // #7
    k_csr<<<(N + 7) / 8, 256>>>(N);                         // #8
    k_bpr<<<(B + 7) / 8, 256>>>(idx1, idx2, negi, B);       // #9
    k_final<<<1, 1>>>((float*)d_out, 1.0f / (float)B);      // #10
}